// round 4
// baseline (speedup 1.0000x reference)
#include <cuda_runtime.h>
#include <cstdint>
#include <cstddef>

#define BATCH 1024
#define LSEQ  512
#define DIM   64
#define KCAP  8
#define NEGV  (-65535.0f)
#define NTHREADS 256
#define SSS 65          // padded S row stride (banks distinct in hs step)

// ---- shared memory layout (float offsets) ----
#define WT_OFF    0                       // W^T [512][8]           4096
#define XB_OFF    4096                    // X dbl-buf 2x32x64      4096 (aliased w/ CPART)
#define CPART_OFF 4096                    // pass1 partials [8][512] (after X dead)
#define SS_OFF    8192                    // S [64][65]             4160
#define CP_OFF    (SS_OFF + 64*SSS)       // C' [8][64]             512
#define CS_OFF    (CP_OFF + 512)          // Cs / high [8][64]      512
#define SCALE_OFF (CS_OFF + 512)          // squash scale [64]      64
#define HST_OFF   (SCALE_OFF + 64)        // hs^T [64][8]           512
#define SMEM_FLOATS (HST_OFF + 512)       // 13952 floats
#define SMEM_BYTES  (SMEM_FLOATS * 4)     // 55808 B -> 4 CTAs/SM

__device__ float g_B[KCAP * LSEQ];
__device__ float g_scratch[BATCH * KCAP * LSEQ];   // per-batch deltas (16MB)
__device__ float g_part[64 * KCAP * LSEQ];         // stage-1 reduction partials

__device__ __forceinline__ void cp_async16(uint32_t sa, const void* ga) {
    asm volatile("cp.async.cg.shared.global [%0], [%1], 16;" :: "r"(sa), "l"(ga));
}
__device__ __forceinline__ void cp_commit() {
    asm volatile("cp.async.commit_group;" ::: "memory");
}
template<int N>
__device__ __forceinline__ void cp_wait() {
    asm volatile("cp.async.wait_group %0;" :: "n"(N) : "memory");
}
__device__ __forceinline__ unsigned long long pack2(float v) {
    unsigned long long r;
    asm("mov.b64 %0, {%1, %1};" : "=l"(r) : "r"(__float_as_uint(v)));
    return r;
}
__device__ __forceinline__ void fma2(unsigned long long& acc,
                                     unsigned long long a, unsigned long long b) {
    asm("fma.rn.f32x2 %0, %1, %2, %0;" : "+l"(acc) : "l"(a), "l"(b));
}
__device__ __forceinline__ float lo2(unsigned long long v) {
    unsigned int a, b_;
    asm("mov.b64 {%0, %1}, %2;" : "=r"(a), "=r"(b_) : "l"(v));
    return __uint_as_float(a);
}
__device__ __forceinline__ float hi2(unsigned long long v) {
    unsigned int a, b_;
    asm("mov.b64 {%0, %1}, %2;" : "=r"(a), "=r"(b_) : "l"(v));
    return __uint_as_float(b_);
}

// One routing iteration, one batch per CTA. 256 threads, 4 CTAs/SM.
template<int LAST>
__global__ void __launch_bounds__(NTHREADS, 4)
route_kernel(const float* __restrict__ X, const float* __restrict__ Sg,
             const int* __restrict__ seqlen, float* __restrict__ out)
{
    extern __shared__ float sm[];
    const int tid  = threadIdx.x;
    const int w    = tid >> 5;          // 8 warps
    const int lane = tid & 31;
    const int b    = blockIdx.x;
    const float* Xg = X + (size_t)b * (LSEQ * DIM);
    const int slen = seqlen[b];

    const uint32_t xs_base = (uint32_t)__cvta_generic_to_shared(&sm[XB_OFF]);

    // issue chunk 0 (rows 0..31) into buffer 0 : 512 sectors of 16B
    {
        #pragma unroll
        for (int h = 0; h < 2; h++) {
            int s = tid + h * 256;
            int row = s >> 4, col = s & 15;
            cp_async16(xs_base + (uint32_t)(row * 256 + col * 16),
                       (const void*)(Xg + row * DIM + col * 4));
        }
        cp_commit();
    }

    // stage S into padded smem (float4 global reads)
    #pragma unroll
    for (int i = 0; i < 4; i++) {
        int j = tid + i * 256;            // 0..1023 float4s
        int d = j >> 4, o4 = (j & 15) * 4;
        float4 v = *(const float4*)(Sg + j * 4);
        float* p = &sm[SS_OFF + d * SSS + o4];
        p[0] = v.x; p[1] = v.y; p[2] = v.z; p[3] = v.w;
    }

    // masked softmax: warp k handles capsule row k
    {
        const int k = w;
        float v[16];
        #pragma unroll
        for (int j = 0; j < 16; j++) {
            int l = lane + 32 * j;
            float bv = g_B[k * LSEQ + l];
            v[j] = (l < slen) ? bv : NEGV;
        }
        float m = v[0];
        #pragma unroll
        for (int j = 1; j < 16; j++) m = fmaxf(m, v[j]);
        #pragma unroll
        for (int off = 16; off > 0; off >>= 1)
            m = fmaxf(m, __shfl_xor_sync(0xffffffffu, m, off));
        float s = 0.f;
        #pragma unroll
        for (int j = 0; j < 16; j++) { v[j] = __expf(v[j] - m); s += v[j]; }
        #pragma unroll
        for (int off = 16; off > 0; off >>= 1)
            s += __shfl_xor_sync(0xffffffffu, s, off);
        float inv = 1.0f / s;
        #pragma unroll
        for (int j = 0; j < 16; j++)
            sm[WT_OFF + (lane + 32 * j) * 8 + k] = v[j] * inv;   // W^T[l][k]
    }
    __syncthreads();   // W^T + S visible; chunk0 issued

    // ---- pass 1: C'[k][d] = sum_l W[k][l] * X[l][d], streamed in 16 chunks ----
    // acc2[dd*4+kp] packs capsules (2kp,2kp+1) for d = 2*lane+dd
    unsigned long long acc2[8];
    #pragma unroll
    for (int i = 0; i < 8; i++) acc2[i] = 0ull;

    #pragma unroll
    for (int c = 0; c < 16; c++) {
        if (c + 1 < 16) {      // prefetch next chunk into other buffer
            int bi = (c + 1) & 1;
            #pragma unroll
            for (int h = 0; h < 2; h++) {
                int s = tid + h * 256;
                int row = s >> 4, col = s & 15;
                cp_async16(xs_base + (uint32_t)(bi * 8192 + row * 256 + col * 16),
                           (const void*)(Xg + ((c + 1) * 32 + row) * DIM + col * 4));
            }
            cp_commit();
            cp_wait<1>();
        } else {
            cp_wait<0>();
        }
        __syncthreads();
        const float* xb = &sm[XB_OFF + (c & 1) * 2048];
        #pragma unroll
        for (int r = 0; r < 4; r++) {
            int lrow = w * 4 + r;
            int l = c * 32 + lrow;
            float2 xv = *(const float2*)&xb[lrow * 64 + 2 * lane];
            ulonglong2 wA = *(const ulonglong2*)&sm[WT_OFF + l * 8];
            ulonglong2 wB = *(const ulonglong2*)&sm[WT_OFF + l * 8 + 4];
            unsigned long long xx0 = pack2(xv.x);
            unsigned long long xx1 = pack2(xv.y);
            fma2(acc2[0], xx0, wA.x); fma2(acc2[1], xx0, wA.y);
            fma2(acc2[2], xx0, wB.x); fma2(acc2[3], xx0, wB.y);
            fma2(acc2[4], xx1, wA.x); fma2(acc2[5], xx1, wA.y);
            fma2(acc2[6], xx1, wB.x); fma2(acc2[7], xx1, wB.y);
        }
        __syncthreads();   // buffer (c&1) free for chunk c+2
    }

    // partials (X buffer dead -> aliased)
    #pragma unroll
    for (int dd = 0; dd < 2; dd++)
        #pragma unroll
        for (int kp = 0; kp < 4; kp++) {
            unsigned long long a = acc2[dd * 4 + kp];
            int d = 2 * lane + dd;
            sm[CPART_OFF + w * 512 + (2 * kp) * 64 + d]     = lo2(a);
            sm[CPART_OFF + w * 512 + (2 * kp + 1) * 64 + d] = hi2(a);
        }
    __syncthreads();

    #pragma unroll
    for (int h = 0; h < 2; h++) {
        int e = tid + h * 256;
        float s = 0.f;
        #pragma unroll
        for (int p = 0; p < 8; p++) s += sm[CPART_OFF + p * 512 + e];
        sm[CP_OFF + e] = s;
    }
    __syncthreads();

    // ---- Cs[k][o] = sum_d C'[k][d] * S[d][o] ----
    {
        int k = tid >> 5, o = tid & 31;
        float a0 = 0.f, a1 = 0.f;
        #pragma unroll
        for (int d = 0; d < 64; d++) {
            float cv = sm[CP_OFF + k * 64 + d];
            a0 += cv * sm[SS_OFF + d * SSS + o];
            a1 += cv * sm[SS_OFF + d * SSS + o + 32];
        }
        sm[CS_OFF + k * 64 + o]      = a0;
        sm[CS_OFF + k * 64 + o + 32] = a1;
    }
    __syncthreads();

    // ---- squash over capsule dim ----
    if (tid < 64) {
        float sq = 0.f;
        #pragma unroll
        for (int k = 0; k < 8; k++) {
            float cv = sm[CS_OFF + k * 64 + tid];
            sq += cv * cv;
        }
        sm[SCALE_OFF + tid] = (sq / (1.0f + sq)) * rsqrtf(sq + 1e-9f);
    }
    __syncthreads();

    #pragma unroll
    for (int h = 0; h < 2; h++) {
        int e = tid + h * 256;
        float hv = sm[SCALE_OFF + (e & 63)] * sm[CS_OFF + e];
        if (LAST) out[(size_t)b * 512 + e] = hv;
        else      sm[CS_OFF + e] = hv;
    }
    if (LAST) return;
    __syncthreads();

    // ---- hs[k][i] = sum_o high[k][o] * S[i][o]  -> hs^T[i][k] ----
    {
        int k = tid >> 5, i = tid & 31;
        float h0 = 0.f, h1 = 0.f;
        #pragma unroll
        for (int o = 0; o < 64; o++) {
            float hv = sm[CS_OFF + k * 64 + o];
            h0 += hv * sm[SS_OFF + i * SSS + o];
            h1 += hv * sm[SS_OFF + (i + 32) * SSS + o];
        }
        sm[HST_OFF + i * 8 + k]        = h0;
        sm[HST_OFF + (i + 32) * 8 + k] = h1;
    }
    __syncthreads();

    // ---- pass 2: delta[k][l] = sum_i hs[k][i] * X[l][i]; X re-read (L2-hit) ----
    #pragma unroll
    for (int h = 0; h < 2; h++) {
        int l = tid + h * 256;
        unsigned long long dacc2[4];
        #pragma unroll
        for (int i = 0; i < 4; i++) dacc2[i] = 0ull;
        const float4* xr = (const float4*)(Xg + l * DIM);
        #pragma unroll
        for (int q = 0; q < 16; q++) {
            float4 x = __ldg(&xr[q]);
            #pragma unroll
            for (int r = 0; r < 4; r++) {
                float xvf = (r == 0) ? x.x : (r == 1) ? x.y : (r == 2) ? x.z : x.w;
                unsigned long long xx = pack2(xvf);
                ulonglong2 hA = *(const ulonglong2*)&sm[HST_OFF + (q * 4 + r) * 8];
                ulonglong2 hB = *(const ulonglong2*)&sm[HST_OFF + (q * 4 + r) * 8 + 4];
                fma2(dacc2[0], xx, hA.x); fma2(dacc2[1], xx, hA.y);
                fma2(dacc2[2], xx, hB.x); fma2(dacc2[3], xx, hB.y);
            }
        }
        float* sc = &g_scratch[(size_t)b * 4096 + l];
        #pragma unroll
        for (int kp = 0; kp < 4; kp++) {
            sc[(2 * kp) * 512]     = lo2(dacc2[kp]);
            sc[(2 * kp + 1) * 512] = hi2(dacc2[kp]);
        }
    }
}

// Deterministic 2-stage cross-batch reduction of deltas into g_B
__global__ void reduce1_kernel() {
    int j = blockIdx.x * 256 + threadIdx.x;      // 0..4095
    int base = blockIdx.y * 16;
    float s = 0.f;
    #pragma unroll
    for (int i = 0; i < 16; i++) s += g_scratch[(size_t)(base + i) * 4096 + j];
    g_part[(size_t)blockIdx.y * 4096 + j] = s;
}
__global__ void reduce2_kernel() {
    int j = blockIdx.x * 256 + threadIdx.x;
    float s = 0.f;
    #pragma unroll
    for (int i = 0; i < 64; i++) s += g_part[(size_t)i * 4096 + j];
    g_B[j] += s;
}

extern "C" void kernel_launch(void* const* d_in, const int* in_sizes, int n_in,
                              void* d_out, int out_size)
{
    const float* X     = (const float*)d_in[0];  // low_capsule [1024,512,64]
    const float* Binit = (const float*)d_in[1];  // B_init [1,8,512]
    const float* S     = (const float*)d_in[2];  // S [64,64]
    const int*   seq   = (const int*)d_in[3];    // seq_len [1024,1]
    float* out = (float*)d_out;

    cudaFuncSetAttribute(route_kernel<0>, cudaFuncAttributeMaxDynamicSharedMemorySize, SMEM_BYTES);
    cudaFuncSetAttribute(route_kernel<1>, cudaFuncAttributeMaxDynamicSharedMemorySize, SMEM_BYTES);

    void* bptr = nullptr;
    cudaGetSymbolAddress(&bptr, g_B);
    cudaMemcpyAsync(bptr, Binit, KCAP * LSEQ * sizeof(float),
                    cudaMemcpyDeviceToDevice, 0);

    // iter 0
    route_kernel<0><<<BATCH, NTHREADS, SMEM_BYTES>>>(X, S, seq, out);
    reduce1_kernel<<<dim3(16, 64), 256>>>();
    reduce2_kernel<<<16, 256>>>();
    // iter 1
    route_kernel<0><<<BATCH, NTHREADS, SMEM_BYTES>>>(X, S, seq, out);
    reduce1_kernel<<<dim3(16, 64), 256>>>();
    reduce2_kernel<<<16, 256>>>();
    // iter 2 (final): writes high
    route_kernel<1><<<BATCH, NTHREADS, SMEM_BYTES>>>(X, S, seq, out);
}

// round 5
// speedup vs baseline: 2.1533x; 2.1533x over previous
#include <cuda_runtime.h>
#include <cstdint>
#include <cstddef>

#define BATCH 1024
#define LSEQ  512
#define DIM   64
#define KCAP  8
#define NEGV  (-65535.0f)
#define NTHREADS 1024
#define XSS 68     // X row stride (floats): conflict-free LDS.64 pass1 / LDS.128 pass2
#define SSS 67     // S row stride: conflict-free for both Cs (o-lanes) and hs (i-lanes)
#define CPS 10     // CPART row stride (8B-aligned u64 stores, ~2-way worst)

// ---- shared memory layout (float offsets) ----
#define WT_OFF     0                        // W^T [512][8]              4096
#define XS_OFF     4096                     // X [512][68]               34816
#define SS_OFF     38912                    // S [64][67]                4288
#define CPART_OFF  43200                    // pass1 partials [16][64][10] 10240
#define CP_OFF     53440                    // C' [8][64]                512
#define P2_OFF     53952                    // 2-way partials [2][512]   1024
#define CS_OFF     54976                    // Cs / high [8][64]         512
#define SCALE_OFF  55488                    // squash scale [64]         64
#define HST_OFF    55552                    // hs^T [64][8]              512
#define SMEM_FLOATS 56064
#define SMEM_BYTES  (SMEM_FLOATS * 4)       // 224256 B (1 CTA/SM)

__device__ float g_B[KCAP * LSEQ];
__device__ float g_scratch[BATCH * KCAP * LSEQ];   // per-batch deltas (16MB)
__device__ float g_part[64 * KCAP * LSEQ];         // stage-1 reduction partials

__device__ __forceinline__ void cp_async16(uint32_t sa, const void* ga) {
    asm volatile("cp.async.cg.shared.global [%0], [%1], 16;" :: "r"(sa), "l"(ga));
}
__device__ __forceinline__ void cp_commit() {
    asm volatile("cp.async.commit_group;" ::: "memory");
}
template<int N>
__device__ __forceinline__ void cp_wait() {
    asm volatile("cp.async.wait_group %0;" :: "n"(N) : "memory");
}
__device__ __forceinline__ unsigned long long pack2(float v) {
    unsigned long long r;
    asm("mov.b64 %0, {%1, %1};" : "=l"(r) : "r"(__float_as_uint(v)));
    return r;
}
__device__ __forceinline__ void fma2(unsigned long long& acc,
                                     unsigned long long a, unsigned long long b) {
    asm("fma.rn.f32x2 %0, %1, %2, %0;" : "+l"(acc) : "l"(a), "l"(b));
}
__device__ __forceinline__ unsigned long long add2(unsigned long long a,
                                                   unsigned long long b) {
    unsigned long long r;
    asm("add.rn.f32x2 %0, %1, %2;" : "=l"(r) : "l"(a), "l"(b));
    return r;
}

// One routing iteration, one batch per CTA. 1024 threads, 1 CTA/SM.
template<int LAST>
__global__ void __launch_bounds__(NTHREADS, 1)
route_kernel(const float* __restrict__ X, const float* __restrict__ Sg,
             const int* __restrict__ seqlen, float* __restrict__ out)
{
    extern __shared__ float sm[];
    const int tid  = threadIdx.x;
    const int w    = tid >> 5;            // 32 warps
    const int lane = tid & 31;
    const int b    = blockIdx.x;
    const float* Xg = X + (size_t)b * (LSEQ * DIM);
    const int slen = seqlen[b];

    // ---- warp-owned X staging: warp w owns rows [16w, 16w+16), 2 groups of 8 ----
    const uint32_t xs_base = (uint32_t)__cvta_generic_to_shared(&sm[XS_OFF]);
    const int row0 = w * 16;
    #pragma unroll
    for (int g2 = 0; g2 < 2; g2++) {
        #pragma unroll
        for (int h = 0; h < 4; h++) {
            int s   = lane + 32 * h;               // 0..127
            int r8  = s >> 4;                      // 0..7
            int col = s & 15;
            int row = row0 + 8 * g2 + r8;
            cp_async16(xs_base + (uint32_t)(row * (XSS * 4) + col * 16),
                       (const void*)(Xg + row * DIM + col * 4));
        }
        cp_commit();
    }

    // stage S [64][67]
    {
        int j = tid;                                // 1024 float4s
        int d = j >> 4, o4 = (j & 15) * 4;
        float4 v = *(const float4*)(Sg + j * 4);
        float* p = &sm[SS_OFF + d * SSS + o4];
        p[0] = v.x; p[1] = v.y; p[2] = v.z; p[3] = v.w;
    }

    // masked softmax: warps 0..7, warp k handles capsule row k
    if (w < 8) {
        const int k = w;
        float v[16];
        #pragma unroll
        for (int j = 0; j < 16; j++) {
            int l = lane + 32 * j;
            float bv = g_B[k * LSEQ + l];
            v[j] = (l < slen) ? bv : NEGV;
        }
        float m = v[0];
        #pragma unroll
        for (int j = 1; j < 16; j++) m = fmaxf(m, v[j]);
        #pragma unroll
        for (int off = 16; off > 0; off >>= 1)
            m = fmaxf(m, __shfl_xor_sync(0xffffffffu, m, off));
        float s = 0.f;
        #pragma unroll
        for (int j = 0; j < 16; j++) { v[j] = __expf(v[j] - m); s += v[j]; }
        #pragma unroll
        for (int off = 16; off > 0; off >>= 1)
            s += __shfl_xor_sync(0xffffffffu, s, off);
        float inv = 1.0f / s;
        #pragma unroll
        for (int j = 0; j < 16; j++)
            sm[WT_OFF + (lane + 32 * j) * 8 + k] = v[j] * inv;   // W^T[l][k]
    }
    __syncthreads();   // W^T + S visible (the ONLY barrier before pass1)

    // ---- pass 1: C'[k][d] = sum_l W[k][l]*X[l][d]; warp-private, no block sync ----
    // acc2[dd*4+kp]: capsule pair (2kp,2kp+1) at d = 2*lane+dd
    unsigned long long acc2[8];
    #pragma unroll
    for (int i = 0; i < 8; i++) acc2[i] = 0ull;

    #pragma unroll
    for (int g2 = 0; g2 < 2; g2++) {
        if (g2 == 0) cp_wait<1>(); else cp_wait<0>();
        __syncwarp();
        #pragma unroll
        for (int r = 0; r < 8; r++) {
            int l = row0 + 8 * g2 + r;
            float2 xv = *(const float2*)&sm[XS_OFF + l * XSS + 2 * lane];
            ulonglong2 wA = *(const ulonglong2*)&sm[WT_OFF + l * 8];       // broadcast
            ulonglong2 wB = *(const ulonglong2*)&sm[WT_OFF + l * 8 + 4];
            unsigned long long xx0 = pack2(xv.x);
            unsigned long long xx1 = pack2(xv.y);
            fma2(acc2[0], xx0, wA.x); fma2(acc2[1], xx0, wA.y);
            fma2(acc2[2], xx0, wB.x); fma2(acc2[3], xx0, wB.y);
            fma2(acc2[4], xx1, wA.x); fma2(acc2[5], xx1, wA.y);
            fma2(acc2[6], xx1, wB.x); fma2(acc2[7], xx1, wB.y);
        }
    }

    // two-wave cross-warp reduction into CPART [16][64][10] (layout [d][k], u64 pairs)
    if (w < 16) {
        #pragma unroll
        for (int dd = 0; dd < 2; dd++)
            #pragma unroll
            for (int kp = 0; kp < 4; kp++) {
                int d = 2 * lane + dd;
                *(unsigned long long*)&sm[CPART_OFF + w * 640 + d * CPS + 2 * kp]
                    = acc2[dd * 4 + kp];
            }
    }
    __syncthreads();
    if (w >= 16) {
        int p = w - 16;
        #pragma unroll
        for (int dd = 0; dd < 2; dd++)
            #pragma unroll
            for (int kp = 0; kp < 4; kp++) {
                int d = 2 * lane + dd;
                unsigned long long* ptr =
                    (unsigned long long*)&sm[CPART_OFF + p * 640 + d * CPS + 2 * kp];
                *ptr = add2(*ptr, acc2[dd * 4 + kp]);
            }
    }
    __syncthreads();
    if (tid < 512) {
        int k = tid >> 6, d = tid & 63;
        float s = 0.f;
        #pragma unroll
        for (int p = 0; p < 16; p++) s += sm[CPART_OFF + p * 640 + d * CPS + k];
        sm[CP_OFF + k * 64 + d] = s;
    }
    __syncthreads();

    // ---- Cs[k][o] = sum_d C'[k][d]*S[d][o], split over d-halves ----
    {
        int k = tid >> 7, idx = tid & 127;
        int o = idx & 63, dh = idx >> 6;
        float a = 0.f;
        #pragma unroll
        for (int dd = 0; dd < 32; dd++) {
            int d = dh * 32 + dd;
            a += sm[CP_OFF + k * 64 + d] * sm[SS_OFF + d * SSS + o];
        }
        sm[P2_OFF + dh * 512 + k * 64 + o] = a;
    }
    __syncthreads();
    if (tid < 512) sm[CS_OFF + tid] = sm[P2_OFF + tid] + sm[P2_OFF + 512 + tid];
    __syncthreads();

    // ---- squash over capsule dim ----
    if (tid < 64) {
        float sq = 0.f;
        #pragma unroll
        for (int k = 0; k < 8; k++) {
            float cv = sm[CS_OFF + k * 64 + tid];
            sq += cv * cv;
        }
        sm[SCALE_OFF + tid] = (sq / (1.0f + sq)) * rsqrtf(sq + 1e-9f);
    }
    __syncthreads();

    if (tid < 512) {
        float hv = sm[SCALE_OFF + (tid & 63)] * sm[CS_OFF + tid];
        if (LAST) out[(size_t)b * 512 + tid] = hv;
        else      sm[CS_OFF + tid] = hv;
    }
    if (LAST) return;
    __syncthreads();

    // ---- hs[k][i] = sum_o high[k][o]*S[i][o], split over o-halves -> hs^T[i][k] ----
    {
        int k = tid >> 7, idx = tid & 127;
        int i = idx & 63, oh = idx >> 6;
        float h = 0.f;
        #pragma unroll
        for (int oo = 0; oo < 32; oo++) {
            int o = oh * 32 + oo;
            h += sm[CS_OFF + k * 64 + o] * sm[SS_OFF + i * SSS + o];
        }
        sm[P2_OFF + oh * 512 + i * 8 + k] = h;
    }
    __syncthreads();
    if (tid < 512) sm[HST_OFF + tid] = sm[P2_OFF + tid] + sm[P2_OFF + 512 + tid];
    __syncthreads();

    // ---- pass 2: delta[k][l] = sum_i hs[k][i]*X[l][i]; thread pair splits k ----
    {
        int row = tid >> 1, ks = tid & 1;     // ks: capsules [4ks, 4ks+4)
        unsigned long long dacc2[2] = {0ull, 0ull};
        #pragma unroll
        for (int q = 0; q < 16; q++) {
            float4 x = *(const float4*)&sm[XS_OFF + row * XSS + q * 4];
            #pragma unroll
            for (int r = 0; r < 4; r++) {
                float xvf = (r == 0) ? x.x : (r == 1) ? x.y : (r == 2) ? x.z : x.w;
                unsigned long long xx = pack2(xvf);
                ulonglong2 hA = *(const ulonglong2*)&sm[HST_OFF + (q * 4 + r) * 8 + 4 * ks];
                fma2(dacc2[0], xx, hA.x);
                fma2(dacc2[1], xx, hA.y);
            }
        }
        float* sc = &g_scratch[(size_t)b * 4096 + row];
        unsigned int u0, u1, u2, u3;
        asm("mov.b64 {%0, %1}, %2;" : "=r"(u0), "=r"(u1) : "l"(dacc2[0]));
        asm("mov.b64 {%0, %1}, %2;" : "=r"(u2), "=r"(u3) : "l"(dacc2[1]));
        sc[(4 * ks + 0) * 512] = __uint_as_float(u0);
        sc[(4 * ks + 1) * 512] = __uint_as_float(u1);
        sc[(4 * ks + 2) * 512] = __uint_as_float(u2);
        sc[(4 * ks + 3) * 512] = __uint_as_float(u3);
    }
}

// Deterministic 2-stage cross-batch reduction of deltas into g_B
__global__ void reduce1_kernel() {
    int j = blockIdx.x * 256 + threadIdx.x;      // 0..4095
    int base = blockIdx.y * 16;
    float s = 0.f;
    #pragma unroll
    for (int i = 0; i < 16; i++) s += g_scratch[(size_t)(base + i) * 4096 + j];
    g_part[(size_t)blockIdx.y * 4096 + j] = s;
}
__global__ void reduce2_kernel() {
    int j = blockIdx.x * 256 + threadIdx.x;
    float s = 0.f;
    #pragma unroll
    for (int i = 0; i < 64; i++) s += g_part[(size_t)i * 4096 + j];
    g_B[j] += s;
}

extern "C" void kernel_launch(void* const* d_in, const int* in_sizes, int n_in,
                              void* d_out, int out_size)
{
    const float* X     = (const float*)d_in[0];  // low_capsule [1024,512,64]
    const float* Binit = (const float*)d_in[1];  // B_init [1,8,512]
    const float* S     = (const float*)d_in[2];  // S [64,64]
    const int*   seq   = (const int*)d_in[3];    // seq_len [1024,1]
    float* out = (float*)d_out;

    cudaFuncSetAttribute(route_kernel<0>, cudaFuncAttributeMaxDynamicSharedMemorySize, SMEM_BYTES);
    cudaFuncSetAttribute(route_kernel<1>, cudaFuncAttributeMaxDynamicSharedMemorySize, SMEM_BYTES);

    void* bptr = nullptr;
    cudaGetSymbolAddress(&bptr, g_B);
    cudaMemcpyAsync(bptr, Binit, KCAP * LSEQ * sizeof(float),
                    cudaMemcpyDeviceToDevice, 0);

    // iter 0
    route_kernel<0><<<BATCH, NTHREADS, SMEM_BYTES>>>(X, S, seq, out);
    reduce1_kernel<<<dim3(16, 64), 256>>>();
    reduce2_kernel<<<16, 256>>>();
    // iter 1
    route_kernel<0><<<BATCH, NTHREADS, SMEM_BYTES>>>(X, S, seq, out);
    reduce1_kernel<<<dim3(16, 64), 256>>>();
    reduce2_kernel<<<16, 256>>>();
    // iter 2 (final): writes high
    route_kernel<1><<<BATCH, NTHREADS, SMEM_BYTES>>>(X, S, seq, out);
}